// round 3
// baseline (speedup 1.0000x reference)
#include <cuda_runtime.h>
#include <cuda_bf16.h>

// Problem constants (fixed shapes)
#define B_DIM 2
#define N_DIM 1024
#define S_DIM 256          // SINGLE_DIM
#define P_DIM 64           // PAIR_DIM
#define MAX_REL 32
#define EMBED_ROWS (2 * MAX_REL + 1)   // 65
#define LN_EPS 1e-5f

// Scratch for projections: (B*N, 64) each -> __device__ globals (no cudaMalloc allowed).
__device__ float g_proj_i[B_DIM * N_DIM * P_DIM];
__device__ float g_proj_j[B_DIM * N_DIM * P_DIM];

// ---------------------------------------------------------------------------
// Kernel A: fused projection GEMM.
// Block = 16 rows staged in shared, 256 threads:
//   col    = t & 63      -> output column
//   half   = (t>>6) & 1  -> W_i (0) or W_j (1)
//   rowgrp = t >> 7      -> rows [8*rowgrp, 8*rowgrp+8)
// Each thread: 8-row accumulator, 256-deep dot. W streamed once per block.
// 128 blocks x 8 warps -> much better fill than previous 4-warp version.
// ---------------------------------------------------------------------------
#define ROWS_PER_BLK 16

__global__ __launch_bounds__(256, 4)
void proj_kernel(const float* __restrict__ single_repr,
                 const float* __restrict__ W,
                 float* __restrict__ proj_i,
                 float* __restrict__ proj_j)
{
    __shared__ float sh[ROWS_PER_BLK][S_DIM];

    const int t    = threadIdx.x;          // 0..255
    const int row0 = blockIdx.x * ROWS_PER_BLK;

    // Cooperative load: 16*256 floats = 1024 float4, 256 threads -> 4 each.
    const float4* s4  = reinterpret_cast<const float4*>(single_repr + (size_t)row0 * S_DIM);
    float4*       sh4 = reinterpret_cast<float4*>(&sh[0][0]);
#pragma unroll
    for (int k = 0; k < 4; ++k)
        sh4[t + 256 * k] = s4[t + 256 * k];
    __syncthreads();

    const int col    = t & 63;
    const int half   = (t >> 6) & 1;       // 0 -> W_i, 1 -> W_j
    const int rowgrp = t >> 7;             // 0 or 1 -> rows 0-7 / 8-15
    const float* Wp  = W + (size_t)half * S_DIM * P_DIM + col;
    const float* shr = &sh[rowgrp * 8][0];

    float acc[8];
#pragma unroll
    for (int r = 0; r < 8; ++r) acc[r] = 0.f;

#pragma unroll 4
    for (int d = 0; d < S_DIM; ++d) {
        const float w = Wp[(size_t)d * P_DIM];
#pragma unroll
        for (int r = 0; r < 8; ++r)
            acc[r] = fmaf(shr[r * S_DIM + d], w, acc[r]);
    }

    float* out = half ? proj_j : proj_i;
#pragma unroll
    for (int r = 0; r < 8; ++r)
        out[(size_t)(row0 + rowgrp * 8 + r) * P_DIM + col] = acc[r];
}

// ---------------------------------------------------------------------------
// Kernel B: pairwise LayerNorm + ReLU + rel-pos embedding.
// One block per (b, i). 8 warps; each warp handles TWO j-rows per iteration
// (16 lanes per row, float4 per lane; 4-round butterfly covers both rows).
//
// L1 optimization: the embed LDS is eliminated for ~94% of iterations.
// For fixed i, only j in [i-32, i+31] needs a table lookup; outside that
// window rel clips to -32/+32 whose embed rows are held in registers
// (e_lo4 / e_hi4). Window membership depends only on warp-uniform j, so
// the branch is non-divergent and the LDS simply never issues.
// ---------------------------------------------------------------------------
__global__ __launch_bounds__(256, 6)
void pair_kernel(const float* __restrict__ proj_i,
                 const float* __restrict__ proj_j,
                 const float* __restrict__ bias,
                 const float* __restrict__ gamma,
                 const float* __restrict__ beta,
                 const float* __restrict__ embed,
                 float* __restrict__ out)
{
    __shared__ float sh_embed[EMBED_ROWS * P_DIM];   // 16.25 KB

    const int bi = blockIdx.x;            // 0 .. B*N-1
    const int bb = bi >> 10;              // batch index
    const int i  = bi & (N_DIM - 1);      // position i

    // Stage embed table in shared (used only inside the +-32 window).
    {
        const float4* e4  = reinterpret_cast<const float4*>(embed);
        float4*       se4 = reinterpret_cast<float4*>(sh_embed);
        for (int k = threadIdx.x; k < (EMBED_ROWS * P_DIM) / 4; k += 256)
            se4[k] = e4[k];
    }

    const int warp  = threadIdx.x >> 5;
    const int lane  = threadIdx.x & 31;
    const int group = lane >> 4;          // which of the two j-rows
    const int sub   = lane & 15;          // float4 slot within the 64-wide row

    // Per-lane constants for row i.
    float4 pi = reinterpret_cast<const float4*>(proj_i + (size_t)bi * P_DIM)[sub];
    {
        const float4 b4 = reinterpret_cast<const float4*>(bias)[sub];
        pi.x += b4.x; pi.y += b4.y; pi.z += b4.z; pi.w += b4.w;
    }
    const float4 g4  = reinterpret_cast<const float4*>(gamma)[sub];
    const float4 be4 = reinterpret_cast<const float4*>(beta)[sub];

    // Register-cached boundary embed rows: rel=-32 -> row 0, rel=+32 -> row 64.
    const float4 e_lo4 = reinterpret_cast<const float4*>(embed)[sub];
    const float4 e_hi4 = reinterpret_cast<const float4*>(embed + (EMBED_ROWS - 1) * P_DIM)[sub];

    __syncthreads();

    const float4* pj_base = reinterpret_cast<const float4*>(
        proj_j + (size_t)bb * N_DIM * P_DIM) + group * (P_DIM / 4) + sub;
    float4* out_base = reinterpret_cast<float4*>(
        out + (size_t)bi * N_DIM * P_DIM) + group * (P_DIM / 4) + sub;

    const int j0 = 2 * warp;
#pragma unroll 4
    for (int it = 0; it < N_DIM / 16; ++it) {
        const int j = j0 + it * 16;       // this lane's row is j + group
        const float4 pj = pj_base[(size_t)j * (P_DIM / 4)];

        float4 v;
        v.x = pi.x + pj.x;
        v.y = pi.y + pj.y;
        v.z = pi.z + pj.z;
        v.w = pi.w + pj.w;

        float s  = (v.x + v.y) + (v.z + v.w);
        float sq = fmaf(v.x, v.x, fmaf(v.y, v.y, fmaf(v.z, v.z, v.w * v.w)));
#pragma unroll
        for (int off = 8; off > 0; off >>= 1) {
            s  += __shfl_xor_sync(0xFFFFFFFFu, s,  off);
            sq += __shfl_xor_sync(0xFFFFFFFFu, sq, off);
        }

        const float mu  = s * (1.f / P_DIM);
        const float var = fmaf(sq, 1.f / P_DIM, -mu * mu);
        const float inv = rsqrtf(var + LN_EPS);

        // Embed lookup: warp-uniform window test (j is uniform across warp).
        // Rows touched this iteration: j and j+1. Interior lookup needed only
        // when (j - i) is in [-32, 31].
        const int dji = j - i;
        float4 e;
        if (dji >= -MAX_REL && dji < MAX_REL) {
            int rel = dji + group;
            rel = (rel < -MAX_REL) ? -MAX_REL : (rel > MAX_REL ? MAX_REL : rel);
            e = reinterpret_cast<const float4*>(sh_embed + (rel + MAX_REL) * P_DIM)[sub];
        } else {
            e = (dji < 0) ? e_lo4 : e_hi4;
        }

        float4 y;
        y.x = fmaxf((v.x - mu) * inv * g4.x + be4.x, 0.f) + e.x;
        y.y = fmaxf((v.y - mu) * inv * g4.y + be4.y, 0.f) + e.y;
        y.z = fmaxf((v.z - mu) * inv * g4.z + be4.z, 0.f) + e.z;
        y.w = fmaxf((v.w - mu) * inv * g4.w + be4.w, 0.f) + e.w;

        out_base[(size_t)j * (P_DIM / 4)] = y;
    }
}

// ---------------------------------------------------------------------------
extern "C" void kernel_launch(void* const* d_in, const int* in_sizes, int n_in,
                              void* d_out, int out_size)
{
    const float* single_repr = (const float*)d_in[0];  // (2,1024,256)
    const float* W           = (const float*)d_in[1];  // (512,64)
    const float* bias        = (const float*)d_in[2];  // (64,)
    const float* gamma       = (const float*)d_in[3];  // (64,)
    const float* beta        = (const float*)d_in[4];  // (64,)
    const float* embed       = (const float*)d_in[5];  // (65,64)
    float* out = (float*)d_out;                        // (2,1024,1024,64)

    float* proj_i_ptr; float* proj_j_ptr;
    cudaGetSymbolAddress((void**)&proj_i_ptr, g_proj_i);
    cudaGetSymbolAddress((void**)&proj_j_ptr, g_proj_j);

    const int total_rows = B_DIM * N_DIM;  // 2048

    proj_kernel<<<total_rows / ROWS_PER_BLK, 256>>>(single_repr, W, proj_i_ptr, proj_j_ptr);
    pair_kernel<<<total_rows, 256>>>(proj_i_ptr, proj_j_ptr, bias, gamma, beta, embed, out);
}

// round 8
// speedup vs baseline: 1.5207x; 1.5207x over previous
#include <cuda_runtime.h>
#include <cuda_bf16.h>

// Problem constants (fixed shapes)
#define B_DIM 2
#define N_DIM 1024
#define S_DIM 256          // SINGLE_DIM
#define P_DIM 64           // PAIR_DIM
#define MAX_REL 32
#define EMBED_ROWS (2 * MAX_REL + 1)   // 65
#define LN_EPS 1e-5f

// Scratch for projections: (B*N, 64) each -> __device__ globals (no cudaMalloc allowed).
__device__ float g_proj_i[B_DIM * N_DIM * P_DIM];
__device__ float g_proj_j[B_DIM * N_DIM * P_DIM];

// ---------------------------------------------------------------------------
// Kernel A: fused projection GEMM.
// Block = 16 rows staged in shared, 256 threads:
//   col = t & 63, half = (t>>6)&1 (W_i / W_j), rowgrp = t>>7 (8 rows each).
// d-loop unrolled x16 -> 16 independent W loads in flight (latency hiding).
// ---------------------------------------------------------------------------
#define ROWS_PER_BLK 16

__global__ __launch_bounds__(256, 4)
void proj_kernel(const float* __restrict__ single_repr,
                 const float* __restrict__ W,
                 float* __restrict__ proj_i,
                 float* __restrict__ proj_j)
{
    __shared__ float sh[ROWS_PER_BLK][S_DIM];

    const int t    = threadIdx.x;          // 0..255
    const int row0 = blockIdx.x * ROWS_PER_BLK;

    const float4* s4  = reinterpret_cast<const float4*>(single_repr + (size_t)row0 * S_DIM);
    float4*       sh4 = reinterpret_cast<float4*>(&sh[0][0]);
#pragma unroll
    for (int k = 0; k < 4; ++k)
        sh4[t + 256 * k] = s4[t + 256 * k];
    __syncthreads();

    const int col    = t & 63;
    const int half   = (t >> 6) & 1;       // 0 -> W_i, 1 -> W_j
    const int rowgrp = t >> 7;             // rows [8*rowgrp, 8*rowgrp+8)
    const float* Wp  = W + (size_t)half * S_DIM * P_DIM + col;
    const float* shr = &sh[rowgrp * 8][0];

    float acc[8];
#pragma unroll
    for (int r = 0; r < 8; ++r) acc[r] = 0.f;

#pragma unroll 16
    for (int d = 0; d < S_DIM; ++d) {
        const float w = Wp[(size_t)d * P_DIM];
#pragma unroll
        for (int r = 0; r < 8; ++r)
            acc[r] = fmaf(shr[r * S_DIM + d], w, acc[r]);
    }

    float* out = half ? proj_j : proj_i;
#pragma unroll
    for (int r = 0; r < 8; ++r)
        out[(size_t)(row0 + rowgrp * 8 + r) * P_DIM + col] = acc[r];
}

// ---------------------------------------------------------------------------
// Kernel B: pairwise LayerNorm + ReLU + rel-pos embedding.
// One block per (b,i). 8 warps; warp handles TWO j-rows per iteration
// (16 lanes/row, float4/lane; 4-round butterfly reduces both rows at once).
//
// Embed handling WITHOUT shared memory and WITHOUT per-iteration branching:
// warp's 64 iterations split into three phases by warp-uniform bounds:
//   j < i-32   -> clipped embed row 0  (register-resident)
//   window     -> true lookup from L2  (<= 4 iterations)
//   j > i+31   -> clipped embed row 64 (register-resident)
// e_lo / e_hi live ranges don't overlap -> low register count.
// No smem, no __syncthreads -> occupancy bound only by regs.
// Output stored with __stcs (evict-first): write-once data stays out of
// L2's hot set, protecting proj_j (re-read 1024x) and embed.
// ---------------------------------------------------------------------------
__device__ __forceinline__ void pair_body(
    const float4 pj, const float4 pi, const float4 g4, const float4 be4,
    const float4 e, float4* __restrict__ outp)
{
    float4 v;
    v.x = pi.x + pj.x;
    v.y = pi.y + pj.y;
    v.z = pi.z + pj.z;
    v.w = pi.w + pj.w;

    float s  = (v.x + v.y) + (v.z + v.w);
    float sq = fmaf(v.x, v.x, fmaf(v.y, v.y, fmaf(v.z, v.z, v.w * v.w)));
#pragma unroll
    for (int off = 8; off > 0; off >>= 1) {
        s  += __shfl_xor_sync(0xFFFFFFFFu, s,  off);
        sq += __shfl_xor_sync(0xFFFFFFFFu, sq, off);
    }

    const float mu  = s * (1.f / P_DIM);
    const float var = fmaf(sq, 1.f / P_DIM, -mu * mu);
    const float inv = rsqrtf(var + LN_EPS);

    float4 y;
    y.x = fmaxf((v.x - mu) * inv * g4.x + be4.x, 0.f) + e.x;
    y.y = fmaxf((v.y - mu) * inv * g4.y + be4.y, 0.f) + e.y;
    y.z = fmaxf((v.z - mu) * inv * g4.z + be4.z, 0.f) + e.z;
    y.w = fmaxf((v.w - mu) * inv * g4.w + be4.w, 0.f) + e.w;

    __stcs(outp, y);
}

__global__ __launch_bounds__(256, 7)
void pair_kernel(const float* __restrict__ proj_i,
                 const float* __restrict__ proj_j,
                 const float* __restrict__ bias,
                 const float* __restrict__ gamma,
                 const float* __restrict__ beta,
                 const float* __restrict__ embed,
                 float* __restrict__ out)
{
    const int bi = blockIdx.x;            // 0 .. B*N-1
    const int bb = bi >> 10;              // batch index
    const int i  = bi & (N_DIM - 1);      // position i

    const int warp  = threadIdx.x >> 5;
    const int lane  = threadIdx.x & 31;
    const int group = lane >> 4;          // which of the two j-rows
    const int sub   = lane & 15;          // float4 slot within the 64-wide row

    // Per-lane constants for row i.
    float4 pi = reinterpret_cast<const float4*>(proj_i + (size_t)bi * P_DIM)[sub];
    {
        const float4 b4 = reinterpret_cast<const float4*>(bias)[sub];
        pi.x += b4.x; pi.y += b4.y; pi.z += b4.z; pi.w += b4.w;
    }
    const float4 g4  = reinterpret_cast<const float4*>(gamma)[sub];
    const float4 be4 = reinterpret_cast<const float4*>(beta)[sub];

    const float4* pj_base = reinterpret_cast<const float4*>(
        proj_j + (size_t)bb * N_DIM * P_DIM) + group * (P_DIM / 4) + sub;
    float4* out_base = reinterpret_cast<float4*>(
        out + (size_t)bi * N_DIM * P_DIM) + group * (P_DIM / 4) + sub;
    const float4* emb4 = reinterpret_cast<const float4*>(embed);

    const int j0 = 2 * warp;              // warp's residue; j = j0 + 16*it

    // Phase bounds (warp-uniform):
    //   interior window: j in [i-32, i+31]  (<= 4 of the 64 iterations)
    const int d1  = i - MAX_REL - j0;                 // j >= i-32  <=> 16it >= d1
    int itA = (d1 <= 0) ? 0 : ((d1 + 15) >> 4);
    if (itA > 64) itA = 64;
    const int d2  = i + MAX_REL - 1 - j0;             // j <= i+31  <=> 16it <= d2
    int itB = (d2 < 0) ? 0 : ((d2 >> 4) + 1);
    if (itB > 64) itB = 64;
    if (itB < itA) itB = itA;

    int it = 0;

    // Phase 1: j < i-32 -> embed row 0 (rel clipped to -32), register-resident.
    if (itA > 0) {
        const float4 e_lo = emb4[sub];
        for (; it < itA; ++it) {
            const int j = j0 + it * 16;
            const float4 pj = pj_base[(size_t)j * (P_DIM / 4)];
            pair_body(pj, pi, g4, be4, e_lo, &out_base[(size_t)j * (P_DIM / 4)]);
        }
    }

    // Phase 2: interior window -> true lookup (upper clip for group=1 at edge).
    for (; it < itB; ++it) {
        const int j = j0 + it * 16;
        int rel = j - i + group;
        if (rel > MAX_REL) rel = MAX_REL;
        const float4 e = emb4[(rel + MAX_REL) * (P_DIM / 4) + sub];
        const float4 pj = pj_base[(size_t)j * (P_DIM / 4)];
        pair_body(pj, pi, g4, be4, e, &out_base[(size_t)j * (P_DIM / 4)]);
    }

    // Phase 3: j > i+31 -> embed row 64 (rel clipped to +32), register-resident.
    if (it < 64) {
        const float4 e_hi = emb4[(EMBED_ROWS - 1) * (P_DIM / 4) + sub];
        for (; it < 64; ++it) {
            const int j = j0 + it * 16;
            const float4 pj = pj_base[(size_t)j * (P_DIM / 4)];
            pair_body(pj, pi, g4, be4, e_hi, &out_base[(size_t)j * (P_DIM / 4)]);
        }
    }
}

// ---------------------------------------------------------------------------
extern "C" void kernel_launch(void* const* d_in, const int* in_sizes, int n_in,
                              void* d_out, int out_size)
{
    const float* single_repr = (const float*)d_in[0];  // (2,1024,256)
    const float* W           = (const float*)d_in[1];  // (512,64)
    const float* bias        = (const float*)d_in[2];  // (64,)
    const float* gamma       = (const float*)d_in[3];  // (64,)
    const float* beta        = (const float*)d_in[4];  // (64,)
    const float* embed       = (const float*)d_in[5];  // (65,64)
    float* out = (float*)d_out;                        // (2,1024,1024,64)

    float* proj_i_ptr; float* proj_j_ptr;
    cudaGetSymbolAddress((void**)&proj_i_ptr, g_proj_i);
    cudaGetSymbolAddress((void**)&proj_j_ptr, g_proj_j);

    const int total_rows = B_DIM * N_DIM;  // 2048

    proj_kernel<<<total_rows / ROWS_PER_BLK, 256>>>(single_repr, W, proj_i_ptr, proj_j_ptr);
    pair_kernel<<<total_rows, 256>>>(proj_i_ptr, proj_j_ptr, bias, gamma, beta, embed, out);
}

// round 14
// speedup vs baseline: 1.6083x; 1.0576x over previous
#include <cuda_runtime.h>
#include <cuda_bf16.h>

// Problem constants (fixed shapes)
#define B_DIM 2
#define N_DIM 1024
#define S_DIM 256          // SINGLE_DIM
#define P_DIM 64           // PAIR_DIM
#define MAX_REL 32
#define EMBED_ROWS (2 * MAX_REL + 1)   // 65
#define LN_EPS 1e-5f

// Scratch (__device__ globals; no cudaMalloc allowed):
// u = proj_i + b/2, v = proj_j + b/2   (each (B*N, 64))
__device__ float g_u[B_DIM * N_DIM * P_DIM];
__device__ float g_v[B_DIM * N_DIM * P_DIM];
// Per-row sums / sums-of-squares: rows 0..2047 = u, 2048..4095 = v
__device__ float g_s[2 * B_DIM * N_DIM];
__device__ float g_q[2 * B_DIM * N_DIM];
// Per-(b,i,j) layernorm stats: {mu, inv_std}
__device__ float2 g_ms[(size_t)B_DIM * N_DIM * N_DIM];

// ---------------------------------------------------------------------------
// K1: fused projection GEMM. Writes u = x@W_i + b/2, v = x@W_j + b/2.
// ---------------------------------------------------------------------------
#define ROWS_PER_BLK 16

__global__ __launch_bounds__(256, 4)
void proj_kernel(const float* __restrict__ single_repr,
                 const float* __restrict__ W,
                 const float* __restrict__ bias)
{
    __shared__ float sh[ROWS_PER_BLK][S_DIM];

    const int t    = threadIdx.x;          // 0..255
    const int row0 = blockIdx.x * ROWS_PER_BLK;

    const float4* s4  = reinterpret_cast<const float4*>(single_repr + (size_t)row0 * S_DIM);
    float4*       sh4 = reinterpret_cast<float4*>(&sh[0][0]);
#pragma unroll
    for (int k = 0; k < 4; ++k)
        sh4[t + 256 * k] = s4[t + 256 * k];
    __syncthreads();

    const int col    = t & 63;
    const int half   = (t >> 6) & 1;       // 0 -> W_i, 1 -> W_j
    const int rowgrp = t >> 7;             // rows [8*rowgrp, 8*rowgrp+8)
    const float* Wp  = W + (size_t)half * S_DIM * P_DIM + col;
    const float* shr = &sh[rowgrp * 8][0];

    float acc[8];
#pragma unroll
    for (int r = 0; r < 8; ++r) acc[r] = 0.f;

#pragma unroll 16
    for (int d = 0; d < S_DIM; ++d) {
        const float w = Wp[(size_t)d * P_DIM];
#pragma unroll
        for (int r = 0; r < 8; ++r)
            acc[r] = fmaf(shr[r * S_DIM + d], w, acc[r]);
    }

    const float hb = 0.5f * bias[col];
    float* out = half ? g_v : g_u;
#pragma unroll
    for (int r = 0; r < 8; ++r)
        out[(size_t)(row0 + rowgrp * 8 + r) * P_DIM + col] = acc[r] + hb;
}

// ---------------------------------------------------------------------------
// K2: per-row sum and sum-of-squares for u (rows 0..2047) and v (2048..4095).
// One warp per row; shuffles fine here (tiny kernel).
// ---------------------------------------------------------------------------
__global__ __launch_bounds__(256)
void rowstat_kernel()
{
    const int row  = blockIdx.x * 8 + (threadIdx.x >> 5);   // 0..4095
    const int lane = threadIdx.x & 31;
    const float* src = (row < B_DIM * N_DIM)
        ? g_u + (size_t)row * P_DIM
        : g_v + (size_t)(row - B_DIM * N_DIM) * P_DIM;

    const float2 x = reinterpret_cast<const float2*>(src)[lane];
    float s = x.x + x.y;
    float q = fmaf(x.x, x.x, x.y * x.y);
#pragma unroll
    for (int off = 16; off > 0; off >>= 1) {
        s += __shfl_xor_sync(0xFFFFFFFFu, s, off);
        q += __shfl_xor_sync(0xFFFFFFFFu, q, off);
    }
    if (lane == 0) { g_s[row] = s; g_q[row] = q; }
}

// ---------------------------------------------------------------------------
// K3: musig GEMM. D_ij = u_i . v_j (K=64), then
//   mu  = (Su_i + Sv_j)/64
//   var = (Qu_i + Qv_j + 2 D_ij)/64 - mu^2
//   inv = rsqrt(var + eps)
// Tile 64x64 per block, 256 threads, each thread 4x4 outputs at
// (i = i0+ty+16r, j = j0+tx+16c) -> coalesced float2 stores.
// V staged transposed in smem for conflict-free reads.
// ---------------------------------------------------------------------------
__global__ __launch_bounds__(256, 2)
void musig_kernel()
{
    __shared__ float U[64][64];    // U[i_local][k]
    __shared__ float Vt[64][64];   // Vt[k][j_local]
    __shared__ float ssu[64], squ[64], ssv[64], sqv[64];

    const int b  = blockIdx.z;
    const int i0 = blockIdx.y * 64;
    const int j0 = blockIdx.x * 64;
    const int t  = threadIdx.x;
    const int tx = t & 15;
    const int ty = t >> 4;

    // Load U tile (row-major) : 4096 floats = 1024 float4.
    {
        const float4* usrc = reinterpret_cast<const float4*>(
            g_u + ((size_t)b * N_DIM + i0) * P_DIM);
        float4* ud = reinterpret_cast<float4*>(&U[0][0]);
#pragma unroll
        for (int k = 0; k < 4; ++k)
            ud[t + 256 * k] = usrc[t + 256 * k];
    }
    // Load V tile transposed.
    {
        const float4* vsrc = reinterpret_cast<const float4*>(
            g_v + ((size_t)b * N_DIM + j0) * P_DIM);
#pragma unroll
        for (int k = 0; k < 4; ++k) {
            const int idx = t + 256 * k;        // 0..1023 float4s
            const int j   = idx >> 4;           // row 0..63
            const int kk  = (idx & 15) * 4;     // k offset
            const float4 v4 = vsrc[idx];
            Vt[kk + 0][j] = v4.x;
            Vt[kk + 1][j] = v4.y;
            Vt[kk + 2][j] = v4.z;
            Vt[kk + 3][j] = v4.w;
        }
    }
    // Row stats slices.
    if (t < 64) {
        ssu[t] = g_s[b * N_DIM + i0 + t];
        squ[t] = g_q[b * N_DIM + i0 + t];
    } else if (t < 128) {
        const int j = t - 64;
        ssv[j] = g_s[B_DIM * N_DIM + b * N_DIM + j0 + j];
        sqv[j] = g_q[B_DIM * N_DIM + b * N_DIM + j0 + j];
    }
    __syncthreads();

    float acc[4][4];
#pragma unroll
    for (int r = 0; r < 4; ++r)
#pragma unroll
        for (int c = 0; c < 4; ++c) acc[r][c] = 0.f;

#pragma unroll 4
    for (int k = 0; k < 64; ++k) {
        float a[4], bb[4];
#pragma unroll
        for (int r = 0; r < 4; ++r) a[r]  = U[ty + 16 * r][k];
#pragma unroll
        for (int c = 0; c < 4; ++c) bb[c] = Vt[k][tx + 16 * c];
#pragma unroll
        for (int r = 0; r < 4; ++r)
#pragma unroll
            for (int c = 0; c < 4; ++c)
                acc[r][c] = fmaf(a[r], bb[c], acc[r][c]);
    }

    const float inv64 = 1.f / P_DIM;
#pragma unroll
    for (int r = 0; r < 4; ++r) {
        const int il = ty + 16 * r;
#pragma unroll
        for (int c = 0; c < 4; ++c) {
            const int jl = tx + 16 * c;
            const float mu  = (ssu[il] + ssv[jl]) * inv64;
            const float ex2 = (squ[il] + sqv[jl] + 2.f * acc[r][c]) * inv64;
            const float var = ex2 - mu * mu;
            float2 ms;
            ms.x = mu;
            ms.y = rsqrtf(var + LN_EPS);
            g_ms[((size_t)b * N_DIM + (i0 + il)) * N_DIM + (j0 + jl)] = ms;
        }
    }
}

// ---------------------------------------------------------------------------
// K4: pairwise normalize + ReLU + rel-pos embedding. ZERO shuffles:
// (mu, inv) read as a broadcast float2 from g_ms. Same three-phase embed
// structure as before (register-resident clipped rows outside the window).
// ---------------------------------------------------------------------------
__device__ __forceinline__ void pair_body(
    const float4 pj, const float4 pi, const float4 g4, const float4 be4,
    const float4 e, const float2 ms, float4* __restrict__ outp)
{
    const float mu  = ms.x;
    const float inv = ms.y;
    float4 y;
    y.x = fmaxf(((pi.x + pj.x) - mu) * inv * g4.x + be4.x, 0.f) + e.x;
    y.y = fmaxf(((pi.y + pj.y) - mu) * inv * g4.y + be4.y, 0.f) + e.y;
    y.z = fmaxf(((pi.z + pj.z) - mu) * inv * g4.z + be4.z, 0.f) + e.z;
    y.w = fmaxf(((pi.w + pj.w) - mu) * inv * g4.w + be4.w, 0.f) + e.w;
    __stcs(outp, y);
}

__global__ __launch_bounds__(256, 7)
void pair_kernel(const float* __restrict__ bias_unused,
                 const float* __restrict__ gamma,
                 const float* __restrict__ beta,
                 const float* __restrict__ embed,
                 float* __restrict__ out)
{
    const int bi = blockIdx.x;            // 0 .. B*N-1
    const int bb = bi >> 10;              // batch index
    const int i  = bi & (N_DIM - 1);      // position i

    const int warp  = threadIdx.x >> 5;
    const int lane  = threadIdx.x & 31;
    const int group = lane >> 4;          // which of the two j-rows
    const int sub   = lane & 15;          // float4 slot within the 64-wide row

    // Per-lane constants for row i (bias already folded into u/v).
    const float4 pi  = reinterpret_cast<const float4*>(g_u + (size_t)bi * P_DIM)[sub];
    const float4 g4  = reinterpret_cast<const float4*>(gamma)[sub];
    const float4 be4 = reinterpret_cast<const float4*>(beta)[sub];

    const float4* pj_base = reinterpret_cast<const float4*>(
        g_v + (size_t)bb * N_DIM * P_DIM) + group * (P_DIM / 4) + sub;
    float4* out_base = reinterpret_cast<float4*>(
        out + (size_t)bi * N_DIM * P_DIM) + group * (P_DIM / 4) + sub;
    const float4* emb4 = reinterpret_cast<const float4*>(embed);
    const float2* ms_base = &g_ms[(size_t)bi * N_DIM + group];

    const int j0 = 2 * warp;              // warp's residue; j = j0 + 16*it

    // Phase bounds (warp-uniform): interior window j in [i-32, i+31].
    const int d1  = i - MAX_REL - j0;
    int itA = (d1 <= 0) ? 0 : ((d1 + 15) >> 4);
    if (itA > 64) itA = 64;
    const int d2  = i + MAX_REL - 1 - j0;
    int itB = (d2 < 0) ? 0 : ((d2 >> 4) + 1);
    if (itB > 64) itB = 64;
    if (itB < itA) itB = itA;

    int it = 0;

    // Phase 1: j < i-32 -> embed row 0, register-resident.
    if (itA > 0) {
        const float4 e_lo = emb4[sub];
#pragma unroll 2
        for (; it < itA; ++it) {
            const int j = j0 + it * 16;
            const float4 pj = pj_base[(size_t)j * (P_DIM / 4)];
            const float2 ms = ms_base[j];
            pair_body(pj, pi, g4, be4, e_lo, ms, &out_base[(size_t)j * (P_DIM / 4)]);
        }
    }

    // Phase 2: interior window -> true lookup (upper clip for group=1 at edge).
    for (; it < itB; ++it) {
        const int j = j0 + it * 16;
        int rel = j - i + group;
        if (rel > MAX_REL) rel = MAX_REL;
        const float4 e = emb4[(rel + MAX_REL) * (P_DIM / 4) + sub];
        const float4 pj = pj_base[(size_t)j * (P_DIM / 4)];
        const float2 ms = ms_base[j];
        pair_body(pj, pi, g4, be4, e, ms, &out_base[(size_t)j * (P_DIM / 4)]);
    }

    // Phase 3: j > i+31 -> embed row 64, register-resident.
    if (it < 64) {
        const float4 e_hi = emb4[(EMBED_ROWS - 1) * (P_DIM / 4) + sub];
#pragma unroll 2
        for (; it < 64; ++it) {
            const int j = j0 + it * 16;
            const float4 pj = pj_base[(size_t)j * (P_DIM / 4)];
            const float2 ms = ms_base[j];
            pair_body(pj, pi, g4, be4, e_hi, ms, &out_base[(size_t)j * (P_DIM / 4)]);
        }
    }
}

// ---------------------------------------------------------------------------
extern "C" void kernel_launch(void* const* d_in, const int* in_sizes, int n_in,
                              void* d_out, int out_size)
{
    const float* single_repr = (const float*)d_in[0];  // (2,1024,256)
    const float* W           = (const float*)d_in[1];  // (512,64)
    const float* bias        = (const float*)d_in[2];  // (64,)
    const float* gamma       = (const float*)d_in[3];  // (64,)
    const float* beta        = (const float*)d_in[4];  // (64,)
    const float* embed       = (const float*)d_in[5];  // (65,64)
    float* out = (float*)d_out;                        // (2,1024,1024,64)

    const int total_rows = B_DIM * N_DIM;  // 2048

    proj_kernel<<<total_rows / ROWS_PER_BLK, 256>>>(single_repr, W, bias);
    rowstat_kernel<<<(2 * total_rows) / 8, 256>>>();
    {
        dim3 grid(N_DIM / 64, N_DIM / 64, B_DIM);
        musig_kernel<<<grid, 256>>>();
    }
    pair_kernel<<<total_rows, 256>>>(bias, gamma, beta, embed, out);
}